// round 17
// baseline (speedup 1.0000x reference)
#include <cuda_runtime.h>
#include <cuda_fp16.h>
#include <cstdint>

#define T_TOK 8192
#define HDIM  1024
#define NEXP  8

#define BM 128
#define BN 128
#define BK 64
#define NITER 16        // 1024 / 64
#define NSTAGE 3
#define GEMM_CTAS_TOTAL (4 * 8 * 64 * 2)   // 4 launches x grid(8,64,2)

// ---------------- device scratch ----------------
__device__ int   g_cur[NEXP];            // per-expert token cursors (= counts)
__device__ int   g_fin;                  // reset ticket across all GEMM CTAs
__device__ float g_gate[T_TOK];
__device__ int   g_tok[NEXP * T_TOK];    // per-expert token lists
__device__ __half g_xh[(size_t)T_TOK * HDIM];        // token order
__device__ __half g_wh[(size_t)NEXP * HDIM * HDIM];  // [e][n][k]

// ---------------- helpers ----------------
__device__ __forceinline__ uint32_t smem_u32(const void* p) {
    uint32_t a;
    asm("{ .reg .u64 t; cvta.to.shared.u64 t, %1; cvt.u32.u64 %0, t; }" : "=r"(a) : "l"(p));
    return a;
}
__device__ __forceinline__ void cp16(uint32_t dst, const void* src) {
    asm volatile("cp.async.cg.shared.global [%0], [%1], 16;" :: "r"(dst), "l"(src));
}
__device__ __forceinline__ void cp_commit() {
    asm volatile("cp.async.commit_group;" ::: "memory");
}
template <int N>
__device__ __forceinline__ void cp_wait() {
    asm volatile("cp.async.wait_group %0;" :: "n"(N) : "memory");
}
#define LDSM4(R, addr) \
    asm volatile("ldmatrix.sync.aligned.m8n8.x4.shared.b16 {%0,%1,%2,%3}, [%4];" \
                 : "=r"((R)[0]), "=r"((R)[1]), "=r"((R)[2]), "=r"((R)[3]) : "r"(addr))
#define MMA16816(D, A, B0, B1) \
    asm volatile("mma.sync.aligned.m16n8k16.row.col.f32.f16.f16.f32 " \
                 "{%0,%1,%2,%3}, {%4,%5,%6,%7}, {%8,%9}, {%0,%1,%2,%3};" \
                 : "+f"((D)[0]), "+f"((D)[1]), "+f"((D)[2]), "+f"((D)[3]) \
                 : "r"((A)[0]), "r"((A)[1]), "r"((A)[2]), "r"((A)[3]), "r"(B0), "r"(B1))

// ============ kernel 1: router + x fp16 convert (token lists via atomics) ===
__global__ __launch_bounds__(256)
void router_kernel(const float* __restrict__ x,
                   const float* __restrict__ rw,
                   const float* __restrict__ rb) {
    __shared__ float rws[NEXP][1028];
    const int tid = threadIdx.x;
    const int lane = tid & 31;

#pragma unroll
    for (int i = 0; i < 32; i++) {
        int idx = tid + i * 256;
        rws[idx & 7][idx >> 3] = rw[idx];
    }
    __syncthreads();

    int gwarp = blockIdx.x * 8 + (tid >> 5);
    const float* xr = x + (size_t)gwarp * HDIM;
    __half* hp = g_xh + (size_t)gwarp * HDIM;
    float acc[NEXP];
#pragma unroll
    for (int e = 0; e < NEXP; e++) acc[e] = 0.f;

#pragma unroll
    for (int i = 0; i < HDIM / 128; i++) {
        int h = (i * 32 + lane) * 4;
        float4 xv = *reinterpret_cast<const float4*>(xr + h);
        __half2 c0 = __floats2half2_rn(xv.x, xv.y);
        __half2 c1 = __floats2half2_rn(xv.z, xv.w);
        uint2 pk;
        pk.x = *reinterpret_cast<uint32_t*>(&c0);
        pk.y = *reinterpret_cast<uint32_t*>(&c1);
        *reinterpret_cast<uint2*>(hp + h) = pk;
#pragma unroll
        for (int e = 0; e < NEXP; e++) {
            float4 wv = *reinterpret_cast<const float4*>(&rws[e][h]);
            acc[e] += xv.x * wv.x + xv.y * wv.y + xv.z * wv.z + xv.w * wv.w;
        }
    }
#pragma unroll
    for (int e = 0; e < NEXP; e++) {
#pragma unroll
        for (int off = 16; off > 0; off >>= 1)
            acc[e] += __shfl_xor_sync(0xffffffffu, acc[e], off);
    }
    if (lane == 0) {
        float logit[NEXP];
        float best = -1e30f;
        int   bi = 0;
#pragma unroll
        for (int e = 0; e < NEXP; e++) {
            logit[e] = acc[e] + rb[e];
            if (logit[e] > best) { best = logit[e]; bi = e; }
        }
        float s = 0.f;
#pragma unroll
        for (int e = 0; e < NEXP; e++) s += expf(logit[e] - best);
        g_gate[gwarp] = 1.0f / s;
        int slot = atomicAdd(&g_cur[bi], 1);
        g_tok[bi * T_TOK + slot] = gwarp;
    }
}

// ============ kernel 2: W transpose + fp16 convert (per expert-pair) ========
__global__ __launch_bounds__(256)
void convw_kernel(const float* __restrict__ ew, int ebase) {
    __shared__ float tile[64][33];
    int bxc = blockIdx.x;                  // 0..1023 = 2 experts x 32n x 16k
    int e  = ebase + (bxc >> 9);
    int n0 = ((bxc >> 4) & 31) * 32;
    int k0 = (bxc & 15) * 64;
    int tid = threadIdx.x;
    int tx = tid & 31, ty = tid >> 5;      // 32 x 8
    const float* W = ew + (size_t)e * HDIM * HDIM;
#pragma unroll
    for (int p = 0; p < 8; p++)
        tile[ty + p * 8][tx] = W[(size_t)(k0 + ty + p * 8) * HDIM + n0 + tx];
    __syncthreads();
    int l  = tid & 31;        // k-pair: k = 2*l
    int nr = tid >> 5;        // 0..7
    uint32_t* w32 = reinterpret_cast<uint32_t*>(g_wh);
#pragma unroll
    for (int q = 0; q < 4; q++) {
        int n = nr + q * 8;
        __half2 h = __floats2half2_rn(tile[2 * l][n], tile[2 * l + 1][n]);
        size_t idx = ((size_t)e * HDIM + (n0 + n)) * (HDIM / 2) + (k0 / 2 + l);
        w32[idx] = *reinterpret_cast<uint32_t*>(&h);
    }
}

// ============ kernel 3: grouped fp16 HMMA GEMM (per expert-pair) ============
static constexpr uint32_t OFF_B    = 49152;   // 3 x 16KB A buffers first
static constexpr uint32_t OFF_TOK  = 98304;
static constexpr uint32_t OFF_GATE = 98816;
static constexpr uint32_t SMEM_TOTAL = 99328;

__device__ __forceinline__ void issue_stage(int j, int tid, const int* sTok, int n0,
                                            size_t ebase, uint32_t sbase) {
    int kin = j * BK;
    int buf = j % NSTAGE;
    const __half* Bb = g_wh + ebase;
    uint32_t as = sbase + (uint32_t)buf * 16384;
    uint32_t bs = sbase + OFF_B + (uint32_t)buf * 16384;
#pragma unroll
    for (int i = 0; i < 4; i++) {
        int op = tid + i * 256;
        int r = op >> 3, c = op & 7;
        cp16(as + r * 128 + ((c * 16) ^ ((r & 7) << 4)),
             g_xh + (size_t)sTok[r] * HDIM + kin + c * 8);
    }
#pragma unroll
    for (int i = 0; i < 4; i++) {
        int op = tid + i * 256;
        int r = op >> 3, c = op & 7;
        cp16(bs + r * 128 + ((c * 16) ^ ((r & 7) << 4)),
             Bb + (size_t)(n0 + r) * HDIM + kin + c * 8);
    }
    cp_commit();
}

__global__ __launch_bounds__(256, 2)
void moe_gemm_kernel(const float* __restrict__ eb, float* __restrict__ out, int ebase) {
    extern __shared__ __align__(1024) char smem[];
    const int tid = threadIdx.x;
    const int e = ebase + blockIdx.z;
    const int cnt = g_cur[e];
    const int m0 = blockIdx.y * BM;

    if (m0 < cnt) {
        const int rows_valid = min(BM, cnt - m0);
        const int n0 = blockIdx.x * BN;
        const uint32_t sbase = smem_u32(smem);
        const size_t ebase_w = (size_t)e * HDIM * HDIM;
        int* sTok = (int*)(smem + OFF_TOK);
        float* sGate = (float*)(smem + OFF_GATE);

        if (tid < 128) {
            int tok = (tid < rows_valid) ? g_tok[e * T_TOK + m0 + tid] : 0;
            sTok[tid] = tok;
            sGate[tid] = g_gate[tok];
        }
        __syncthreads();

        issue_stage(0, tid, sTok, n0, ebase_w, sbase);
        issue_stage(1, tid, sTok, n0, ebase_w, sbase);
        issue_stage(2, tid, sTok, n0, ebase_w, sbase);

        const int lane = tid & 31, wid = tid >> 5;
        const int warp_m = (wid >> 1) * 32;
        const int warp_n = (wid & 1) * 64;
        const int idx = lane & 7, grp = lane >> 3;

        const int arow = warp_m + (grp & 1) * 8 + idx;
        const uint32_t axor = (uint32_t)((arow & 7) << 4);
        const uint32_t acsel = (uint32_t)((grp >> 1) * 16);
        const int brow = warp_n + (grp >> 1) * 8 + idx;
        const uint32_t bxor = (uint32_t)((brow & 7) << 4);
        const uint32_t bcsel = (uint32_t)((grp & 1) * 16);

        float acc[2][8][4];
#pragma unroll
        for (int i = 0; i < 2; i++)
#pragma unroll
            for (int j = 0; j < 8; j++)
#pragma unroll
                for (int q = 0; q < 4; q++) acc[i][j][q] = 0.f;

        for (int k = 0; k < NITER; k++) {
            cp_wait<2>();
            __syncthreads();
            int buf = k % NSTAGE;
            uint32_t as = sbase + (uint32_t)buf * 16384;
            uint32_t bs = sbase + OFF_B + (uint32_t)buf * 16384;
#pragma unroll
            for (int step = 0; step < 4; step++) {
                uint32_t kc = (uint32_t)(step * 32);
                uint32_t a[2][4], b[4][4];
#pragma unroll
                for (int mt = 0; mt < 2; mt++)
                    LDSM4(a[mt], as + (uint32_t)(arow + mt * 16) * 128 + ((kc + acsel) ^ axor));
#pragma unroll
                for (int bt = 0; bt < 4; bt++)
                    LDSM4(b[bt], bs + (uint32_t)(brow + bt * 16) * 128 + ((kc + bcsel) ^ bxor));
#pragma unroll
                for (int mt = 0; mt < 2; mt++)
#pragma unroll
                    for (int bt = 0; bt < 4; bt++) {
                        MMA16816(acc[mt][2 * bt],     a[mt], b[bt][0], b[bt][1]);
                        MMA16816(acc[mt][2 * bt + 1], a[mt], b[bt][2], b[bt][3]);
                    }
            }
            __syncthreads();
            if (k + NSTAGE < NITER) issue_stage(k + NSTAGE, tid, sTok, n0, ebase_w, sbase);
            else cp_commit();
        }

        const float* ebias = eb + (size_t)e * HDIM + n0;
        const int colq = (lane & 3) * 2;
#pragma unroll
        for (int mt = 0; mt < 2; mt++) {
            int r_lo = warp_m + mt * 16 + (lane >> 2);
            int r_hi = r_lo + 8;
            bool v_lo = r_lo < rows_valid, v_hi = r_hi < rows_valid;
            int   t_lo = sTok[r_lo],  t_hi = sTok[r_hi];
            float g_lo = sGate[r_lo], g_hi = sGate[r_hi];
            float* o_lo = out + (size_t)t_lo * HDIM + n0;
            float* o_hi = out + (size_t)t_hi * HDIM + n0;
#pragma unroll
            for (int nt = 0; nt < 8; nt++) {
                int col = warp_n + nt * 8 + colq;
                float2 bv = *reinterpret_cast<const float2*>(ebias + col);
                if (v_lo) {
                    float2 v;
                    v.x = g_lo * (acc[mt][nt][0] + bv.x);
                    v.y = g_lo * (acc[mt][nt][1] + bv.y);
                    *reinterpret_cast<float2*>(o_lo + col) = v;
                }
                if (v_hi) {
                    float2 v;
                    v.x = g_hi * (acc[mt][nt][2] + bv.x);
                    v.y = g_hi * (acc[mt][nt][3] + bv.y);
                    *reinterpret_cast<float2*>(o_hi + col) = v;
                }
            }
        }
        cp_wait<0>();
    }

    // replay-state reset ticket (all CTAs of all 4 launches participate)
    __syncthreads();
    if (tid == 0) {
        __threadfence();
        if (atomicAdd(&g_fin, 1) == GEMM_CTAS_TOTAL - 1) {
#pragma unroll
            for (int q = 0; q < NEXP; q++) g_cur[q] = 0;
            g_fin = 0;
            __threadfence();
        }
    }
}

// ---------------- streams/events (static init: outside mem checkpoints) ----
static cudaStream_t s_w, s_g[4];
static cudaEvent_t  ev_fork, ev_r, ev_w[4], ev_g[4];
namespace {
struct HxStreams {
    HxStreams() {
        cudaFree(0);   // init context
        int least = 0, greatest = 0;
        cudaDeviceGetStreamPriorityRange(&least, &greatest);
        cudaStreamCreateWithPriority(&s_w, cudaStreamNonBlocking, greatest);  // W = high prio
        for (int k = 0; k < 4; k++)
            cudaStreamCreateWithPriority(&s_g[k], cudaStreamNonBlocking, least);
        cudaEventCreateWithFlags(&ev_fork, cudaEventDisableTiming);
        cudaEventCreateWithFlags(&ev_r, cudaEventDisableTiming);
        for (int k = 0; k < 4; k++) {
            cudaEventCreateWithFlags(&ev_w[k], cudaEventDisableTiming);
            cudaEventCreateWithFlags(&ev_g[k], cudaEventDisableTiming);
        }
    }
};
static HxStreams g_hxstreams;
}

// ---------------- launch: fork-join pipeline ----------------
extern "C" void kernel_launch(void* const* d_in, const int* in_sizes, int n_in,
                              void* d_out, int out_size) {
    const float* x  = (const float*)d_in[0];
    const float* rw = (const float*)d_in[1];
    const float* rb = (const float*)d_in[2];
    const float* ew = (const float*)d_in[3];
    const float* eb = (const float*)d_in[4];
    float* out = (float*)d_out;

    cudaFuncSetAttribute(moe_gemm_kernel,
                         cudaFuncAttributeMaxDynamicSharedMemorySize, SMEM_TOTAL);

    // fork: W-convert chunks run concurrently with the router
    cudaEventRecord(ev_fork, 0);
    cudaStreamWaitEvent(s_w, ev_fork, 0);
    for (int k = 0; k < 4; k++) {
        convw_kernel<<<1024, 256, 0, s_w>>>(ew, 2 * k);
        cudaEventRecord(ev_w[k], s_w);
    }

    router_kernel<<<T_TOK / 8, 256, 0, 0>>>(x, rw, rb);
    cudaEventRecord(ev_r, 0);

    // per-expert-pair GEMMs on concurrent streams, gated on router + their W
    for (int k = 0; k < 4; k++) {
        cudaStreamWaitEvent(s_g[k], ev_r, 0);
        cudaStreamWaitEvent(s_g[k], ev_w[k], 0);
        moe_gemm_kernel<<<dim3(8, 64, 2), 256, SMEM_TOTAL, s_g[k]>>>(eb, out, 2 * k);
        cudaEventRecord(ev_g[k], s_g[k]);
    }

    // join back to the main stream
    for (int k = 0; k < 4; k++)
        cudaStreamWaitEvent(0, ev_g[k], 0);
}